// round 3
// baseline (speedup 1.0000x reference)
#include <cuda_runtime.h>

#define BB 16
#define TT 96
#define TP1 97
#define HW 16384
#define NSTEP 6
#define MTHR 0.9f

// ---- scratch (device globals; no allocation APIs) ----
__device__ float         g_D[(size_t)BB * HW * TT];  // d[b][p][t], t contiguous (~100MB)
__device__ double        g_delta[BB * TP1];          // idx0 = empty template, always 0
__device__ unsigned char g_used[BB * TP1];
__device__ unsigned char g_topcov[BB * HW];
__device__ float         g_topval[BB * HW];
__device__ int           g_cid[BB];

// ---------------------------------------------------------------------------
__global__ void k_init() {
    int i = threadIdx.x;
    for (int j = i; j < BB * TP1; j += 256) { g_delta[j] = 0.0; g_used[j] = 0; }
    if (i < BB) g_cid[i] = 0;
}

// ---------------------------------------------------------------------------
// Precompute D[b][p][t] = cov ? (x - t*m)^2 - (x - bg)^2 : 0, plus delta0[b][t].
// 256 threads per (b, 64-pixel) tile; 4 templates in flight per iteration,
// unroll 8 -> 32 outstanding load pairs per thread.
__global__ void k_precompute(const float* __restrict__ x,
                             const float* __restrict__ temps,
                             const float* __restrict__ msks,
                             const float* __restrict__ bg) {
    __shared__ float xs[64], eb[64];
    __shared__ float dsm[64][TP1];   // stride 97: conflict-free rows & columns

    const int b   = blockIdx.y;
    const int p0  = blockIdx.x * 64;
    const int tid = threadIdx.x;

    if (tid < 64) {
        float xv = x[b * HW + p0 + tid];
        float bv = bg[p0 + tid];
        xs[tid] = xv;
        float e = xv - bv;
        eb[tid] = e * e;
        g_topcov[b * HW + p0 + tid] = 0;   // fold init here
    }
    __syncthreads();

    const int ts = tid >> 6;     // 0..3 -> four templates per iteration
    const int ps = tid & 63;
    #pragma unroll 8
    for (int t4 = 0; t4 < TT; t4 += 4) {
        int t   = t4 + ts;
        int idx = (b * TT + t) * HW + p0 + ps;
        float tv = __ldg(&temps[idx]);
        float mv = __ldg(&msks[idx]);
        float dd = 0.f;
        if (mv > MTHR) {
            float a = xs[ps] - tv * mv;
            dd = a * a - eb[ps];
        }
        dsm[ps][t] = dd;
    }
    __syncthreads();

    // store D: global index (b*HW+p0)*96 + i fully contiguous in i
    const size_t obase = ((size_t)b * HW + p0) * TT;
    int r = tid / TT, c = tid % TT;        // one div at start, then incremental
    for (int i = tid; i < 64 * TT; i += 256) {
        g_D[obase + i] = dsm[r][c];
        c += 64; r += 2;                    // 256 = 2*96 + 64
        if (c >= TT) { c -= TT; r += 1; }
    }

    // per-t partial sums -> delta0
    if (tid < TT) {
        float s = 0.f;
        #pragma unroll
        for (int p = 0; p < 64; p++) s += dsm[p][tid];
        atomicAdd(&g_delta[b * TP1 + 1 + tid], (double)s);
    }
}

// ---------------------------------------------------------------------------
// argmin over 97 candidates with used-penalty; first-index tie-break (jnp.argmin)
__global__ void k_argmin() {
    int b    = blockIdx.x;
    int lane = threadIdx.x;
    double bestv = 1e300;
    int    besti = TP1;
    for (int t = lane; t < TP1; t += 32) {
        double v = g_used[b * TP1 + t] ? 1e30 : g_delta[b * TP1 + t];
        if (v < bestv) { bestv = v; besti = t; }   // ascending t: earliest on tie
    }
    for (int off = 16; off; off >>= 1) {
        double ov = __shfl_down_sync(0xffffffffu, bestv, off);
        int    oi = __shfl_down_sync(0xffffffffu, besti, off);
        if (ov < bestv || (ov == bestv && oi < besti)) { bestv = ov; besti = oi; }
    }
    if (lane == 0) {
        g_cid[b] = besti;
        if (besti != 0) g_used[b * TP1 + besti] = 1;
    }
}

// ---------------------------------------------------------------------------
// Fused paint + newly-covered detection + delta subtraction for one step.
// 512 threads per 128-pixel tile: group g (128 threads, 96 active in gather)
// handles the 32 pixels of warp-mask g. Chain depth per accumulator ~2.
__global__ void __launch_bounds__(512) k_step(const float* __restrict__ temps,
                                              const float* __restrict__ msks) {
    __shared__ unsigned wmask[4];
    __shared__ float    partial[4][TT];

    const int b   = blockIdx.y;
    const int cid = g_cid[b];
    if (cid == 0) return;                  // empty template: nothing changes
    const int t   = cid - 1;
    const int tid = threadIdx.x;
    const int p0  = blockIdx.x * 128;

    // paint phase: first 128 threads = 128 consecutive pixels
    if (tid < 128) {
        const int q   = b * HW + p0 + tid;
        const int idx = (b * TT + t) * HW + p0 + tid;
        float mv = msks[idx];
        bool nw = false;
        if (mv > MTHR && !g_topcov[q]) {
            g_topval[q] = temps[idx] * mv; // new object goes UNDER existing
            g_topcov[q] = 1;
            nw = true;
        }
        unsigned m = __ballot_sync(0xffffffffu, nw);
        if ((tid & 31) == 0) wmask[tid >> 5] = m;
    }
    __syncthreads();

    if ((wmask[0] | wmask[1] | wmask[2] | wmask[3]) == 0u) return;

    // gather phase: group g handles pixels [p0+g*32, p0+g*32+32)
    const int g  = tid >> 7;
    const int lt = tid & 127;
    const unsigned mm = wmask[g];
    float a0 = 0.f, a1 = 0.f, a2 = 0.f, a3 = 0.f;
    if (mm && lt < TT) {
        const float* dp = g_D + ((size_t)b * HW + p0 + g * 32) * TT + lt;
        #pragma unroll
        for (int j = 0; j < 32; j += 4) {
            if (mm & (1u <<  j     )) a0 += dp[(size_t)(j    ) * TT];
            if (mm & (1u << (j + 1))) a1 += dp[(size_t)(j + 1) * TT];
            if (mm & (1u << (j + 2))) a2 += dp[(size_t)(j + 2) * TT];
            if (mm & (1u << (j + 3))) a3 += dp[(size_t)(j + 3) * TT];
        }
    }
    if (lt < TT) partial[g][lt] = (a0 + a1) + (a2 + a3);
    __syncthreads();

    if (tid < TT) {
        float tot = (partial[0][tid] + partial[1][tid]) +
                    (partial[2][tid] + partial[3][tid]);
        if (tot != 0.f)
            atomicAdd(&g_delta[b * TP1 + 1 + tid], -(double)tot);
    }
}

// ---------------------------------------------------------------------------
__global__ void k_final(const float* __restrict__ bg, float* __restrict__ out) {
    int b = blockIdx.y;
    int p = blockIdx.x * blockDim.x + threadIdx.x;
    int q = b * HW + p;
    out[q] = g_topcov[q] ? g_topval[q] : bg[p];
}

// ---------------------------------------------------------------------------
extern "C" void kernel_launch(void* const* d_in, const int* in_sizes, int n_in,
                              void* d_out, int out_size) {
    const float* x      = (const float*)d_in[0];   // (16,1,128,128)
    const float* temps  = (const float*)d_in[1];   // (16,96,1,128,128)
    const float* msks   = (const float*)d_in[2];   // (16,96,1,128,128)
    const float* bg     = (const float*)d_in[3];   // (1,128,128)
    float* out = (float*)d_out;                    // (16,1,128,128)

    k_init<<<1, 256>>>();
    k_precompute<<<dim3(HW / 64, BB), 256>>>(x, temps, msks, bg);

    for (int s = 0; s < NSTEP; s++) {
        k_argmin<<<BB, 32>>>();
        k_step<<<dim3(HW / 128, BB), 512>>>(temps, msks);
    }
    k_final<<<dim3(HW / 256, BB), 256>>>(bg, out);
}

// round 4
// speedup vs baseline: 1.1654x; 1.1654x over previous
#include <cuda_runtime.h>

#define BB 16
#define TT 96
#define TP1 97
#define HW 16384
#define NSTEP 6
#define MTHR 0.9f

// ---- scratch (device globals; no allocation APIs) ----
__device__ float         g_D[(size_t)BB * HW * TT];  // d[b][p][t], t contiguous (~100MB)
__device__ double        g_delta[BB * TP1];          // idx0 = empty template, always 0
__device__ unsigned char g_topcov[BB * HW];
__device__ float         g_topval[BB * HW];
__device__ int           g_hist[NSTEP * BB];         // selected cid per (step, batch)
__device__ int           g_cnt[NSTEP * BB];          // new-pixel count per (step, batch)
__device__ int           g_list[NSTEP * BB * HW];    // new-pixel indices (~6MB)

// ---------------------------------------------------------------------------
__global__ void k_init() {
    int i = threadIdx.x;
    for (int j = i; j < BB * TP1; j += 256) g_delta[j] = 0.0;
    if (i < NSTEP * BB) g_cnt[i] = 0;
}

// ---------------------------------------------------------------------------
// Precompute D[b][p][t] = cov ? (x - t*m)^2 - (x - bg)^2 : 0, plus delta0[b][t].
// 256 threads per (b, 64-pixel tile); float2 loads, 8 templates per iteration.
__global__ void k_precompute(const float* __restrict__ x,
                             const float* __restrict__ temps,
                             const float* __restrict__ msks,
                             const float* __restrict__ bg) {
    __shared__ float xs[64], eb[64];
    __shared__ float dsm[64][TP1];   // stride 97: conflict-free rows & columns

    const int b   = blockIdx.y;
    const int p0  = blockIdx.x * 64;
    const int tid = threadIdx.x;

    if (tid < 64) {
        float xv = x[b * HW + p0 + tid];
        float bv = bg[p0 + tid];
        xs[tid] = xv;
        float e = xv - bv;
        eb[tid] = e * e;
        g_topcov[b * HW + p0 + tid] = 0;   // fold init here
    }
    __syncthreads();

    const int ts  = tid >> 5;    // 0..7 -> eight templates per iteration
    const int ps2 = tid & 31;    // float2 index: pixels 2*ps2, 2*ps2+1
    #pragma unroll
    for (int t8 = 0; t8 < TT; t8 += 8) {
        int t = t8 + ts;
        const float2* tp = (const float2*)(temps + (size_t)(b * TT + t) * HW + p0) + ps2;
        const float2* mp = (const float2*)(msks  + (size_t)(b * TT + t) * HW + p0) + ps2;
        float2 tv = __ldg(tp);
        float2 mv = __ldg(mp);
        int p = 2 * ps2;
        float d0 = 0.f, d1 = 0.f;
        if (mv.x > MTHR) { float a = xs[p]     - tv.x * mv.x; d0 = a * a - eb[p];     }
        if (mv.y > MTHR) { float a = xs[p + 1] - tv.y * mv.y; d1 = a * a - eb[p + 1]; }
        dsm[p][t]     = d0;
        dsm[p + 1][t] = d1;
    }
    __syncthreads();

    // store D with float4 (6144 floats per tile, fully contiguous)
    const size_t obase = ((size_t)b * HW + p0) * TT;
    for (int i = tid; i < 64 * TT / 4; i += 256) {
        int r = i / 24, c = (i % 24) * 4;
        float4 v = make_float4(dsm[r][c], dsm[r][c + 1], dsm[r][c + 2], dsm[r][c + 3]);
        *(float4*)&g_D[obase + (size_t)i * 4] = v;
    }

    // per-t partial sums -> delta0
    if (tid < TT) {
        float s = 0.f;
        #pragma unroll
        for (int p = 0; p < 64; p++) s += dsm[p][tid];
        atomicAdd(&g_delta[b * TP1 + 1 + tid], (double)s);
    }
}

// ---------------------------------------------------------------------------
// One greedy step: every block recomputes argmin (deterministic, redundant),
// paints its 256 pixels, appends newly covered pixels to the step list.
// On the last step, also writes the final composition for its pixels.
__global__ void k_paint(int s, int last,
                        const float* __restrict__ temps,
                        const float* __restrict__ msks,
                        const float* __restrict__ bg,
                        float* __restrict__ out) {
    __shared__ int s_cid;
    const int b   = blockIdx.y;
    const int tid = threadIdx.x;

    if (tid < 32) {
        double bestv = 1e300;
        int    besti = TP1;
        for (int t = tid; t < TP1; t += 32) {
            double v = g_delta[b * TP1 + t];
            for (int j = 0; j < s; j++)
                if (g_hist[j * BB + b] == t && t != 0) v = 1e30;  // used penalty
            if (v < bestv) { bestv = v; besti = t; }              // earliest on tie
        }
        for (int off = 16; off; off >>= 1) {
            double ov = __shfl_down_sync(0xffffffffu, bestv, off);
            int    oi = __shfl_down_sync(0xffffffffu, besti, off);
            if (ov < bestv || (ov == bestv && oi < besti)) { bestv = ov; besti = oi; }
        }
        if (tid == 0) {
            s_cid = besti;
            if (blockIdx.x == 0) g_hist[s * BB + b] = besti;
        }
    }
    __syncthreads();

    const int cid = s_cid;
    const int p   = blockIdx.x * 256 + tid;
    const int q   = b * HW + p;

    bool nw = false;
    if (cid != 0) {
        const int idx = (b * TT + cid - 1) * HW + p;
        float mv = msks[idx];
        if (mv > MTHR && !g_topcov[q]) {
            g_topval[q] = temps[idx] * mv;   // new object goes UNDER existing
            g_topcov[q] = 1;
            nw = true;
        }
    }

    if (!last) {
        // warp-aggregated append of new pixels to this step's list
        unsigned m = __ballot_sync(0xffffffffu, nw);
        if (m) {
            int lane   = tid & 31;
            int leader = __ffs(m) - 1;
            int base = 0;
            if (lane == leader) base = atomicAdd(&g_cnt[s * BB + b], __popc(m));
            base = __shfl_sync(0xffffffffu, base, leader);
            if (nw) g_list[(s * BB + b) * HW + base + __popc(m & ((1u << lane) - 1))] = p;
        }
    } else {
        out[q] = g_topcov[q] ? g_topval[q] : bg[p];
    }
}

// ---------------------------------------------------------------------------
// delta[b][t] -= sum over this step's new pixels of D[b][p][t].
// 128 threads (96 gather); 32-pixel chunks -> 32 independent loads/thread.
__global__ void __launch_bounds__(128) k_sub(int s) {
    const int b   = blockIdx.y;
    const int cnt = g_cnt[s * BB + b];
    if (cnt == 0) return;
    const int nch = (cnt + 31) >> 5;
    const int t   = threadIdx.x;

    __shared__ int sl[32];
    float a0=0,a1=0,a2=0,a3=0,a4=0,a5=0,a6=0,a7=0;
    bool any = false;

    for (int c = blockIdx.x; c < nch; c += gridDim.x) {
        int nrem = min(32, cnt - c * 32);
        if (t < 32) sl[t] = (t < nrem) ? g_list[(s * BB + b) * HW + c * 32 + t] : 0;
        __syncthreads();
        if (t < TT) {
            const float* Db = g_D + (size_t)b * HW * TT + t;
            if (nrem == 32) {
                #pragma unroll
                for (int j = 0; j < 32; j += 8) {
                    a0 += Db[(size_t)sl[j    ] * TT];
                    a1 += Db[(size_t)sl[j + 1] * TT];
                    a2 += Db[(size_t)sl[j + 2] * TT];
                    a3 += Db[(size_t)sl[j + 3] * TT];
                    a4 += Db[(size_t)sl[j + 4] * TT];
                    a5 += Db[(size_t)sl[j + 5] * TT];
                    a6 += Db[(size_t)sl[j + 6] * TT];
                    a7 += Db[(size_t)sl[j + 7] * TT];
                }
            } else {
                #pragma unroll
                for (int j = 0; j < 32; j++) {
                    if (j < nrem) a0 += Db[(size_t)sl[j] * TT];
                }
            }
            any = true;
        }
        __syncthreads();
    }
    if (any && t < TT) {
        float tot = ((a0 + a1) + (a2 + a3)) + ((a4 + a5) + (a6 + a7));
        atomicAdd(&g_delta[b * TP1 + 1 + t], -(double)tot);
    }
}

// ---------------------------------------------------------------------------
extern "C" void kernel_launch(void* const* d_in, const int* in_sizes, int n_in,
                              void* d_out, int out_size) {
    const float* x      = (const float*)d_in[0];   // (16,1,128,128)
    const float* temps  = (const float*)d_in[1];   // (16,96,1,128,128)
    const float* msks   = (const float*)d_in[2];   // (16,96,1,128,128)
    const float* bg     = (const float*)d_in[3];   // (1,128,128)
    float* out = (float*)d_out;                    // (16,1,128,128)

    k_init<<<1, 256>>>();
    k_precompute<<<dim3(HW / 64, BB), 256>>>(x, temps, msks, bg);

    for (int s = 0; s < NSTEP; s++) {
        int last = (s == NSTEP - 1);
        k_paint<<<dim3(HW / 256, BB), 256>>>(s, last, temps, msks, bg, out);
        if (!last) k_sub<<<dim3(64, BB), 128>>>(s);
    }
}